// round 7
// baseline (speedup 1.0000x reference)
#include <cuda_runtime.h>
#include <math.h>
#include <stdint.h>

#define D   10112
#define H   2048
#define P   62
#define NB  62
#define NBP (NB*P)     // 3844
#define DCH 79         // D / 128

// ---------------- scratch (device globals; no allocation) ----------------
__device__ float g_bigpart[3 * DCH * H];   // split-K partials for the 3 big matvecs
__device__ float g_h1[H];                  // bass hidden1 (post-selu)
__device__ float g_ua0[H];                 // alto  x@aw1[:D] + ab1 (pre-selu shared part)
__device__ float g_ut0[H];                 // tenor x@tw1[:D] + tb1
__device__ float g_p2[64 * H];             // bass layer2 partials
__device__ float g_h2[H];                  // bass hidden2
__device__ float g_lbp[16 * 64];           // bass layer3 partials
__device__ float g_probs1[NB];
__device__ int   g_pitch1[NB];
__device__ float g_gpart[8 * 64 * H];      // stage GEMM split-K partials
__device__ float g_hX2[NB * H];            // stage hidden2
__device__ float g_l3p[62 * 16 * 64];      // stage L3 partials
__device__ float g_flat[NBP];
__device__ float g_probs2[NB];
__device__ int   g_pb2[NB];
__device__ int   g_pa2[NB];

// completion counters (zero-init; last block resets -> replay-safe)
__device__ unsigned g_c_l1[12];
__device__ unsigned g_c_l2[4];
__device__ unsigned g_c_bl3;
__device__ unsigned g_c_gemm[32];
__device__ unsigned g_c_l3[62];

__device__ __forceinline__ float selu_f(float x) {
    const float sc = 1.0507009873554805f;
    const float al = 1.6732632423543772f;
    return x > 0.f ? sc * x : sc * al * expm1f(x);
}

// ================= 1. fused big L1: 3 matvecs + reduce ====================
// grid (4, 79, 3), block 128. z: 0=bass, 1=alto, 2=tenor.
__global__ __launch_bounds__(128, 8) void fused_l1(
        const float* __restrict__ x,
        const float* __restrict__ bw1, const float* __restrict__ bb1,
        const float* __restrict__ aw1, const float* __restrict__ ab1,
        const float* __restrict__ tw1, const float* __restrict__ tb1) {
    __shared__ float sx[128];
    __shared__ bool isLast;
    int t = threadIdx.x;
    int cg = blockIdx.x, c = blockIdx.y, z = blockIdx.z;
    const float* __restrict__ W = (z == 0) ? bw1 : ((z == 1) ? aw1 : tw1);
    int i0 = c * 128;
    sx[t] = x[i0 + t];
    __syncthreads();
    int j4 = cg * 128 + t;
    const float4* __restrict__ W4 = (const float4*)W;
    float4 acc = make_float4(0.f, 0.f, 0.f, 0.f);
#pragma unroll 8
    for (int i = 0; i < 128; ++i) {
        float xv = sx[i];
        float4 w = W4[(size_t)(i0 + i) * (H / 4) + j4];
        acc.x += xv * w.x; acc.y += xv * w.y; acc.z += xv * w.z; acc.w += xv * w.w;
    }
    ((float4*)g_bigpart)[((size_t)z * DCH + c) * (H / 4) + j4] = acc;
    __threadfence();
    if (t == 0) {
        unsigned p = atomicAdd(&g_c_l1[z * 4 + cg], 1u);
        isLast = (p == DCH - 1);
    }
    __syncthreads();
    if (!isLast) return;
    if (t == 0) g_c_l1[z * 4 + cg] = 0;
    const float4* __restrict__ bp4 = (const float4*)g_bigpart;
    float4 s = make_float4(0.f, 0.f, 0.f, 0.f);
#pragma unroll 4
    for (int cc = 0; cc < DCH; ++cc) {
        float4 v = bp4[((size_t)z * DCH + cc) * (H / 4) + j4];
        s.x += v.x; s.y += v.y; s.z += v.z; s.w += v.w;
    }
    if (z == 0) {
        float4 b = ((const float4*)bb1)[j4];
        float4 o;
        o.x = selu_f(s.x + b.x); o.y = selu_f(s.y + b.y);
        o.z = selu_f(s.z + b.z); o.w = selu_f(s.w + b.w);
        ((float4*)g_h1)[j4] = o;
    } else if (z == 1) {
        float4 b = ((const float4*)ab1)[j4];
        ((float4*)g_ua0)[j4] = make_float4(s.x + b.x, s.y + b.y, s.z + b.z, s.w + b.w);
    } else {
        float4 b = ((const float4*)tb1)[j4];
        ((float4*)g_ut0)[j4] = make_float4(s.x + b.x, s.y + b.y, s.z + b.z, s.w + b.w);
    }
}

// ================= 2. bass L2 fused: part + reduce ========================
// grid (4, 64), block 128. chunk = 32 rows.
__global__ __launch_bounds__(128, 8) void l2_fused(const float* __restrict__ W,
                                                   const float* __restrict__ b) {
    __shared__ float sx[32];
    __shared__ bool isLast;
    int t = threadIdx.x;
    int cg = blockIdx.x, c = blockIdx.y;
    int i0 = c * 32;
    if (t < 32) sx[t] = g_h1[i0 + t];
    __syncthreads();
    int j4 = cg * 128 + t;
    const float4* __restrict__ W4 = (const float4*)W;
    float4 acc = make_float4(0.f, 0.f, 0.f, 0.f);
#pragma unroll 8
    for (int i = 0; i < 32; ++i) {
        float xv = sx[i];
        float4 w = W4[(size_t)(i0 + i) * (H / 4) + j4];
        acc.x += xv * w.x; acc.y += xv * w.y; acc.z += xv * w.z; acc.w += xv * w.w;
    }
    ((float4*)g_p2)[(size_t)c * (H / 4) + j4] = acc;
    __threadfence();
    if (t == 0) {
        unsigned p = atomicAdd(&g_c_l2[cg], 1u);
        isLast = (p == 63);
    }
    __syncthreads();
    if (!isLast) return;
    if (t == 0) g_c_l2[cg] = 0;
    const float4* __restrict__ p4 = (const float4*)g_p2;
    float4 s = make_float4(0.f, 0.f, 0.f, 0.f);
#pragma unroll 8
    for (int cc = 0; cc < 64; ++cc) {
        float4 v = p4[(size_t)cc * (H / 4) + j4];
        s.x += v.x; s.y += v.y; s.z += v.z; s.w += v.w;
    }
    float4 bv = ((const float4*)b)[j4];
    float4 o;
    o.x = selu_f(s.x + bv.x); o.y = selu_f(s.y + bv.y);
    o.z = selu_f(s.z + bv.z); o.w = selu_f(s.w + bv.w);
    ((float4*)g_h2)[j4] = o;
}

// ================= 3. bass L3 + softmax + sort, fused =====================
// grid 16, block 256 = 64 n x 4 k-groups of 32 rows.
__global__ __launch_bounds__(256) void bass_l3sort(const float* __restrict__ W3,
                                                   const float* __restrict__ b3) {
    __shared__ float sh[128];
    __shared__ float sred[4][64];
    __shared__ bool isLast;
    __shared__ float pv[64];
    __shared__ float red;
    int kc = blockIdx.x;
    int t = threadIdx.x;
    if (t < 128) sh[t] = g_h2[kc * 128 + t];
    __syncthreads();
    int n = t & 63, kg = t >> 6;
    float acc = 0.f;
    if (n < P) {
        int kb = kc * 128 + kg * 32;
        int ks = kg * 32;
#pragma unroll 8
        for (int k = 0; k < 32; ++k) acc += sh[ks + k] * W3[(kb + k) * P + n];
    }
    sred[kg][n] = acc;
    __syncthreads();
    if (kg == 0) g_lbp[kc * 64 + n] = ((sred[0][n] + sred[1][n]) + sred[2][n]) + sred[3][n];
    __threadfence();
    if (t == 0) {
        unsigned p = atomicAdd(&g_c_bl3, 1u);
        isLast = (p == 15);
    }
    __syncthreads();
    if (!isLast) return;
    if (t == 0) g_c_bl3 = 0;
    // softmax + descending stable sort over 62 (threads t<64 active)
    if (t < 64) {
        float s = 0.f;
#pragma unroll
        for (int c = 0; c < 16; ++c) s += g_lbp[c * 64 + t];
        pv[t] = (t < P) ? (s + b3[t]) : -1e30f;
    }
    __syncthreads();
    if (t == 0) { float mx = -1e30f; for (int i = 0; i < P; ++i) mx = fmaxf(mx, pv[i]); red = mx; }
    __syncthreads();
    float e = 0.f;
    if (t < 64) { e = (t < P) ? expf(pv[t] - red) : 0.f; }
    __syncthreads();
    if (t < 64) pv[t] = e;
    __syncthreads();
    if (t == 0) { float ss = 0.f; for (int i = 0; i < P; ++i) ss += pv[i]; red = ss; }
    __syncthreads();
    if (t < 64) {
        float p = e / red;
        pv[t] = (t < P) ? p : -1.f;
    }
    __syncthreads();
    if (t < P) {
        float p = pv[t];
        int r = 0;
        for (int i = 0; i < P; ++i) {
            float o = pv[i];
            r += (o > p) || (o == p && i < t);
        }
        g_probs1[r] = p;
        g_pitch1[r] = t;
    }
}

// ========== 4. stage L2 GEMM fused: hidden1-on-the-fly + split-K ==========
// grid (32 n-tiles, 8 k-chunks), block 256.
#define GM  64
#define GN  64
#define GKT 32
#define KCH 8
#define KLEN (H / KCH)   // 256
__global__ __launch_bounds__(256) void gemm_fused(const float* __restrict__ B,
                                                  const float* __restrict__ bias,
                                                  const float* __restrict__ W1,
                                                  int stage) {
    __shared__ float sA[GKT][GM + 1];
    __shared__ float sB[GKT][GN];
    __shared__ int spb[64], spa[64];
    __shared__ bool isLast;
    int t = threadIdx.x;
    int n0 = blockIdx.x * GN;
    int kc = blockIdx.y;
    int kbase = kc * KLEN;
    if (t < 64) {
        int mm = t;
        if (mm < NB) {
            if (stage == 0) { spb[mm] = g_pitch1[mm]; spa[mm] = 0; }
            else            { spb[mm] = g_pb2[mm];    spa[mm] = g_pa2[mm]; }
        } else { spb[mm] = 0; spa[mm] = 0; }
    }
    __syncthreads();
    int tx = t & 15, ty = t >> 4;
    float acc[4][4] = {};
    const float* __restrict__ u0 = (stage == 0) ? g_ua0 : g_ut0;
    for (int kt = 0; kt < KLEN; kt += GKT) {
        int k0 = kbase + kt;
#pragma unroll
        for (int r = 0; r < 8; ++r) {
            int idx = t + r * 256;
            int kk = idx & 31, mm = idx >> 5;
            float v = 0.f;
            if (mm < NB) {
                int k = k0 + kk;
                float h = u0[k] + W1[(size_t)(D + spb[mm]) * H + k];
                if (stage == 1) h += W1[(size_t)(D + P + spa[mm]) * H + k];
                v = selu_f(h);
            }
            sA[kk][mm] = v;
        }
#pragma unroll
        for (int r = 0; r < 8; ++r) {
            int idx = t + r * 256;
            int nn = idx & 63, kk = idx >> 6;
            sB[kk][nn] = B[(size_t)(k0 + kk) * H + n0 + nn];
        }
        __syncthreads();
#pragma unroll
        for (int k = 0; k < GKT; ++k) {
            float a[4], b[4];
#pragma unroll
            for (int r = 0; r < 4; ++r) a[r] = sA[k][ty * 4 + r];
#pragma unroll
            for (int c = 0; c < 4; ++c) b[c] = sB[k][tx * 4 + c];
#pragma unroll
            for (int r = 0; r < 4; ++r)
#pragma unroll
                for (int c = 0; c < 4; ++c) acc[r][c] += a[r] * b[c];
        }
        __syncthreads();
    }
#pragma unroll
    for (int r = 0; r < 4; ++r) {
        int m = ty * 4 + r;
#pragma unroll
        for (int c = 0; c < 4; ++c) {
            g_gpart[((size_t)kc * GM + m) * H + n0 + tx * 4 + c] = acc[r][c];
        }
    }
    __threadfence();
    if (t == 0) {
        unsigned p = atomicAdd(&g_c_gemm[blockIdx.x], 1u);
        isLast = (p == KCH - 1);
    }
    __syncthreads();
    if (!isLast) return;
    if (t == 0) g_c_gemm[blockIdx.x] = 0;
    // reduce the 8 partials for this 64-col tile: 62 rows x 16 float4
    const float4* __restrict__ gp4 = (const float4*)g_gpart;
    const float4* __restrict__ b4 = (const float4*)bias;
#pragma unroll
    for (int i = 0; i < 4; ++i) {
        int idx4 = t + i * 256;          // 0 .. 1023 ; need 62*16 = 992
        if (idx4 < NB * 16) {
            int m = idx4 >> 4, n4 = idx4 & 15;
            size_t base = (size_t)m * (H / 4) + (n0 >> 2) + n4;
            float4 s = make_float4(0.f, 0.f, 0.f, 0.f);
#pragma unroll
            for (int c = 0; c < KCH; ++c) {
                float4 v = gp4[((size_t)c * GM + m) * (H / 4) + (n0 >> 2) + n4];
                s.x += v.x; s.y += v.y; s.z += v.z; s.w += v.w;
            }
            float4 bb = b4[(n0 >> 2) + n4];
            float4 o;
            o.x = selu_f(s.x + bb.x); o.y = selu_f(s.y + bb.y);
            o.z = selu_f(s.z + bb.z); o.w = selu_f(s.w + bb.w);
            ((float4*)g_hX2)[base] = o;
        }
    }
}

// ========== 5. stage L3 fused: part + reduce + softmax + scale ============
// grid (62, 16), block 256.
__global__ __launch_bounds__(256) void l3_all(const float* __restrict__ W3,
                                              const float* __restrict__ b3,
                                              int stage) {
    __shared__ float sh[128];
    __shared__ float sred[4][64];
    __shared__ bool isLast;
    __shared__ float vals[64];
    __shared__ float red;
    int m = blockIdx.x;
    int kc = blockIdx.y;
    int t = threadIdx.x;
    if (t < 128) sh[t] = g_hX2[m * H + kc * 128 + t];
    __syncthreads();
    int n = t & 63, kg = t >> 6;
    float acc = 0.f;
    if (n < P) {
        int kb = kc * 128 + kg * 32;
        int ks = kg * 32;
#pragma unroll 8
        for (int k = 0; k < 32; ++k) acc += sh[ks + k] * W3[(kb + k) * P + n];
    }
    sred[kg][n] = acc;
    __syncthreads();
    if (kg == 0) g_l3p[((size_t)m * 16 + kc) * 64 + n] = ((sred[0][n] + sred[1][n]) + sred[2][n]) + sred[3][n];
    __threadfence();
    if (t == 0) {
        unsigned p = atomicAdd(&g_c_l3[m], 1u);
        isLast = (p == 15);
    }
    __syncthreads();
    if (!isLast) return;
    if (t == 0) g_c_l3[m] = 0;
    if (t < 64) {
        float s = 0.f;
#pragma unroll
        for (int c = 0; c < 16; ++c) s += g_l3p[((size_t)m * 16 + c) * 64 + t];
        vals[t] = (t < P) ? (s + b3[t]) : -1e30f;
    }
    __syncthreads();
    if (t == 0) { float mx = -1e30f; for (int i = 0; i < P; ++i) mx = fmaxf(mx, vals[i]); red = mx; }
    __syncthreads();
    float e = 0.f;
    if (t < 64) e = (t < P) ? expf(vals[t] - red) : 0.f;
    __syncthreads();
    if (t < 64) vals[t] = e;
    __syncthreads();
    if (t == 0) { float ss = 0.f; for (int i = 0; i < P; ++i) ss += vals[i]; red = ss; }
    __syncthreads();
    float scale = (stage == 0) ? g_probs1[m] : g_probs2[m];
    if (t < P) g_flat[m * P + t] = (e / red) * scale;
}

// ================= 6. exact top-62 of 3844 by rank count ==================
// grid 61, block 512 = 64 g-values x 8 scan segments
__global__ __launch_bounds__(512) void topk62(int stage, float* __restrict__ out) {
    __shared__ float sv[NBP];
    __shared__ int   pr[8][64];
    int t = threadIdx.x;
    float4* sv4s = (float4*)sv;
    const float4* gf4 = (const float4*)g_flat;
    for (int i = t; i < NBP / 4; i += 512) sv4s[i] = gf4[i];
    __syncthreads();
    int gl = t & 63, seg = t >> 6;
    int g = blockIdx.x * 64 + gl;
    float v = (g < NBP) ? sv[g] : 0.f;
    int q0 = (seg == 0) ? 0 : (121 + (seg - 1) * 120);
    int qn = (seg == 0) ? 121 : 120;
    int r = 0;
    const float4* sv4 = (const float4*)sv;
#pragma unroll 4
    for (int qq = 0; qq < qn; ++qq) {
        int q = q0 + qq;
        float4 o = sv4[q];
        int base = q * 4;
        r += (o.x > v) || (o.x == v && (base + 0) < g);
        r += (o.y > v) || (o.y == v && (base + 1) < g);
        r += (o.z > v) || (o.z == v && (base + 2) < g);
        r += (o.w > v) || (o.w == v && (base + 3) < g);
    }
    pr[seg][gl] = r;
    __syncthreads();
    if (seg == 0 && g < NBP) {
        int rt = 0;
#pragma unroll
        for (int q = 0; q < 8; ++q) rt += pr[q][gl];
        if (rt < NB) {
            int row = g / P, col = g % P;
            if (stage == 0) {
                g_probs2[rt] = v;
                g_pb2[rt] = g_pitch1[row];
                g_pa2[rt] = col;
            } else {
                out[rt * 4 + 0] = v;
                out[rt * 4 + 1] = (float)g_pb2[row];
                out[rt * 4 + 2] = (float)g_pa2[row];
                out[rt * 4 + 3] = (float)col;
            }
        }
    }
}

// ---------------- launch ---------------------------------------------------
extern "C" void kernel_launch(void* const* d_in, const int* in_sizes, int n_in,
                              void* d_out, int out_size) {
    (void)in_sizes; (void)n_in; (void)out_size;
    const float* x   = (const float*)d_in[0];
    const float* bw1 = (const float*)d_in[1];
    const float* bb1 = (const float*)d_in[2];
    const float* bw2 = (const float*)d_in[3];
    const float* bb2 = (const float*)d_in[4];
    const float* bw3 = (const float*)d_in[5];
    const float* bb3 = (const float*)d_in[6];
    const float* aw1 = (const float*)d_in[7];
    const float* ab1 = (const float*)d_in[8];
    const float* aw2 = (const float*)d_in[9];
    const float* ab2 = (const float*)d_in[10];
    const float* aw3 = (const float*)d_in[11];
    const float* ab3 = (const float*)d_in[12];
    const float* tw1 = (const float*)d_in[13];
    const float* tb1 = (const float*)d_in[14];
    const float* tw2 = (const float*)d_in[15];
    const float* tb2 = (const float*)d_in[16];
    const float* tw3 = (const float*)d_in[17];
    const float* tb3 = (const float*)d_in[18];
    float* out = (float*)d_out;

    fused_l1<<<dim3(4, DCH, 3), 128>>>(x, bw1, bb1, aw1, ab1, tw1, tb1);
    l2_fused<<<dim3(4, 64), 128>>>(bw2, bb2);
    bass_l3sort<<<16, 256>>>(bw3, bb3);

    gemm_fused<<<dim3(32, KCH), 256>>>(aw2, ab2, aw1, 0);
    l3_all<<<dim3(NB, 16), 256>>>(aw3, ab3, 0);
    topk62<<<61, 512>>>(0, out);

    gemm_fused<<<dim3(32, KCH), 256>>>(tw2, tb2, tw1, 1);
    l3_all<<<dim3(NB, 16), 256>>>(tw3, tb3, 1);
    topk62<<<61, 512>>>(1, out);
}